// round 11
// baseline (speedup 1.0000x reference)
#include <cuda_runtime.h>
#include <cuda_bf16.h>
#include <math.h>
#include <stdint.h>

#define D_MODEL 1024
#define NHEADS  16
#define HDIM    64
#define BATCH   2
#define SEQ     2048
#define MTOT    (BATCH*SEQ)          // 4096
#define GK      1024
#define NELEM   (MTOT*D_MODEL)       // 4M
#define WELEM   (D_MODEL*D_MODEL)    // 1M

// Scratch (allocation-free rule: static __device__ globals)
__device__ __nv_bfloat16 g_xh[NELEM],  g_xl[NELEM];
__device__ __nv_bfloat16 g_wqh[WELEM], g_wql[WELEM];
__device__ __nv_bfloat16 g_wkh[WELEM], g_wkl[WELEM];
__device__ __nv_bfloat16 g_wvh[WELEM], g_wvl[WELEM];
__device__ __nv_bfloat16 g_woh[WELEM], g_wol[WELEM];
__device__ __nv_bfloat16 g_qh[NELEM],  g_ql[NELEM];
__device__ __nv_bfloat16 g_kh[NELEM],  g_kl[NELEM];
__device__ __nv_bfloat16 g_vh[NELEM],  g_vl[NELEM];
__device__ __nv_bfloat16 g_ath[NELEM], g_atl[NELEM];
__device__ float2 g_trig[SEQ*(HDIM/2)];   // [s][t] -> (cos, sin)

// ===========================================================================
// helpers
// ===========================================================================
__device__ __forceinline__ uint32_t smem_u32(const void* p) {
    uint32_t a;
    asm("{ .reg .u64 t; cvta.to.shared.u64 t, %1; cvt.u32.u64 %0, t; }" : "=r"(a) : "l"(p));
    return a;
}
__device__ __forceinline__ void ldsm_x4(uint32_t* r, uint32_t addr) {
    asm volatile("ldmatrix.sync.aligned.m8n8.x4.shared.b16 {%0,%1,%2,%3}, [%4];"
        : "=r"(r[0]), "=r"(r[1]), "=r"(r[2]), "=r"(r[3]) : "r"(addr));
}
__device__ __forceinline__ void ldsm_x4_t(uint32_t* r, uint32_t addr) {
    asm volatile("ldmatrix.sync.aligned.m8n8.x4.trans.shared.b16 {%0,%1,%2,%3}, [%4];"
        : "=r"(r[0]), "=r"(r[1]), "=r"(r[2]), "=r"(r[3]) : "r"(addr));
}
__device__ __forceinline__ void mma_bf16(float* c, const uint32_t* a, uint32_t b0, uint32_t b1) {
    asm volatile("mma.sync.aligned.m16n8k16.row.col.f32.bf16.bf16.f32 "
        "{%0,%1,%2,%3}, {%4,%5,%6,%7}, {%8,%9}, {%0,%1,%2,%3};"
        : "+f"(c[0]), "+f"(c[1]), "+f"(c[2]), "+f"(c[3])
        : "r"(a[0]), "r"(a[1]), "r"(a[2]), "r"(a[3]), "r"(b0), "r"(b1));
}
__device__ __forceinline__ float ex2f(float x) {
    float y; asm("ex2.approx.f32 %0, %1;" : "=f"(y) : "f"(x)); return y;
}
__device__ __forceinline__ void pack2(float x, float y, uint32_t& h, uint32_t& l) {
    __nv_bfloat162 hh = __floats2bfloat162_rn(x, y);
    float hx = __bfloat162float(hh.x), hy = __bfloat162float(hh.y);
    __nv_bfloat162 ll = __floats2bfloat162_rn(x - hx, y - hy);
    h = *(uint32_t*)&hh; l = *(uint32_t*)&ll;
}

#define CP16(dst, src) \
    asm volatile("cp.async.cg.shared.global [%0], [%1], 16;" :: "r"(dst), "l"(src) : "memory")
#define CPCOMMIT() asm volatile("cp.async.commit_group;" ::: "memory")
#define CPWAIT0()  asm volatile("cp.async.wait_group 0;" ::: "memory")

#define QSCL 0.18033688011112042f   // 0.125 * log2(e)

// ===========================================================================
// trig table: [s][t] -> (cos, sin) of s * 10000^(-2t/64)
// ===========================================================================
__global__ void trig_kernel(float2* __restrict__ trig)
{
    int i = blockIdx.x*blockDim.x + threadIdx.x;
    if (i >= SEQ*(HDIM/2)) return;
    const int t = i & 31;
    const int s = i >> 5;
    const float ang = (float)s * exp2f((float)t * (-2.0f/(float)HDIM) * 13.28771237954945f);
    float sn, cs;
    sincosf(ang, &sn, &cs);
    trig[i] = make_float2(cs, sn);
}

// ===========================================================================
// split_all: fp32 -> bf16 hi/lo for x + 4 weights, one launch.
// ===========================================================================
#define XPAIRS (NELEM/2)
#define WPAIRS (WELEM/2)

__global__ void split_all(const float* __restrict__ x,
                          const float* __restrict__ Wq, const float* __restrict__ Wk,
                          const float* __restrict__ Wv, const float* __restrict__ Wo,
                          __nv_bfloat16* xh, __nv_bfloat16* xl,
                          __nv_bfloat16* wqh, __nv_bfloat16* wql,
                          __nv_bfloat16* wkh, __nv_bfloat16* wkl,
                          __nv_bfloat16* wvh, __nv_bfloat16* wvl,
                          __nv_bfloat16* woh, __nv_bfloat16* wol)
{
    int i = blockIdx.x*blockDim.x + threadIdx.x;
    const int total = XPAIRS + 4*WPAIRS;
    if (i >= total) return;

    const float* src; __nv_bfloat16 *hi, *lo; int j;
    if (i < XPAIRS)                { src = x;  hi = xh;  lo = xl;  j = i; }
    else if (i < XPAIRS+WPAIRS)    { src = Wq; hi = wqh; lo = wql; j = i - XPAIRS; }
    else if (i < XPAIRS+2*WPAIRS)  { src = Wk; hi = wkh; lo = wkl; j = i - XPAIRS - WPAIRS; }
    else if (i < XPAIRS+3*WPAIRS)  { src = Wv; hi = wvh; lo = wvl; j = i - XPAIRS - 2*WPAIRS; }
    else                           { src = Wo; hi = woh; lo = wol; j = i - XPAIRS - 3*WPAIRS; }

    float2 v = *(const float2*)(src + 2*(size_t)j);
    uint32_t h, l;
    pack2(v.x, v.y, h, l);
    ((uint32_t*)hi)[j] = h;
    ((uint32_t*)lo)[j] = l;
}

// ===========================================================================
// swizzles
// ===========================================================================
__device__ __forceinline__ uint32_t sw_off(int row, int chunk) {
    return (uint32_t)(row*64 + ((chunk ^ ((row>>1)&3))<<4));
}
__device__ __forceinline__ uint32_t fsw(int row, int chunk) {
    return (uint32_t)(row*128 + ((chunk ^ (row & 7)) << 4));
}

#define STAGE2 32768
#define GSMEM2 65536

// ===========================================================================
// GEMM mainloop shared by both GEMM kernels (acc += (Ah+Al)(Bh+Bl), 3 passes)
// ===========================================================================
__device__ __forceinline__ void gemm_mainloop(
    uint32_t smb, const __nv_bfloat16* Ah, const __nv_bfloat16* Al,
    const __nv_bfloat16* Bh, const __nv_bfloat16* Bl,
    size_t aoff, size_t boff, const uint32_t* soff,
    int lhalf, int wm, int wn, int l15, int l16, float acc[4][4][4])
{
    // prologue: chunk 0 -> stage 0
    {
        const uint32_t s0 = smb;
        #pragma unroll
        for (int u = 0; u < 2; u++) {
            const int chunk = lhalf*2 + u;
            const size_t ke = (size_t)chunk*8;
            CP16(s0 + 0     + soff[u], Ah + aoff + ke);
            CP16(s0 + 8192  + soff[u], Al + aoff + ke);
            CP16(s0 + 16384 + soff[u], Bh + boff + ke);
            CP16(s0 + 24576 + soff[u], Bl + boff + ke);
        }
        CPCOMMIT();
    }

    for (int ch = 0; ch < 32; ch++) {
        CPWAIT0();
        __syncthreads();

        if (ch < 31) {
            const uint32_t s0 = smb + ((ch+1)&1)*STAGE2;
            #pragma unroll
            for (int u = 0; u < 2; u++) {
                const int chunk = lhalf*2 + u;
                const size_t ke = (size_t)(ch+1)*32 + chunk*8;
                CP16(s0 + 0     + soff[u], Ah + aoff + ke);
                CP16(s0 + 8192  + soff[u], Al + aoff + ke);
                CP16(s0 + 16384 + soff[u], Bh + boff + ke);
                CP16(s0 + 24576 + soff[u], Bl + boff + ke);
            }
            CPCOMMIT();
        }

        const uint32_t st  = smb + (ch&1)*STAGE2;
        const uint32_t uAh = st, uAl = st + 8192, uBh = st + 16384, uBl = st + 24576;

        #pragma unroll
        for (int s = 0; s < 2; s++) {
            const int chunk = s*2 + l16;

            uint32_t bh[2][4], bl[2][4];
            #pragma unroll
            for (int ng = 0; ng < 2; ng++) {
                const int br = wn*32 + ng*16 + l15;
                const uint32_t off = sw_off(br, chunk);
                ldsm_x4(bh[ng], uBh + off);
                ldsm_x4(bl[ng], uBl + off);
            }

            #pragma unroll
            for (int mt = 0; mt < 4; mt++) {
                const int ar = wm*64 + mt*16 + l15;
                const uint32_t off = sw_off(ar, chunk);
                uint32_t ah[4], al[4];
                ldsm_x4(ah, uAh + off);
                ldsm_x4(al, uAl + off);

                #pragma unroll
                for (int nt = 0; nt < 4; nt++) {
                    const int ng = nt >> 1, ix = nt & 1;
                    const uint32_t b0h = bh[ng][ix], b1h = bh[ng][2+ix];
                    const uint32_t b0l = bl[ng][ix], b1l = bl[ng][2+ix];
                    mma_bf16(acc[mt][nt], ah, b0h, b1h);
                    mma_bf16(acc[mt][nt], al, b0h, b1h);
                    mma_bf16(acc[mt][nt], ah, b0l, b1l);
                }
            }
        }
    }
}

// ===========================================================================
// Fused QKV GEMM: grid (24, 32). bcol>>3 selects Wq/Wk/Wv; epilogue applies
// RoPE (q,k; q also scaled) via trig table and writes bf16 hi/lo directly.
// ===========================================================================
__global__ void __launch_bounds__(256, 2) gemm_qkv(const __nv_bfloat16* __restrict__ xh,
                                                const __nv_bfloat16* __restrict__ xl,
                                                const __nv_bfloat16* __restrict__ wqh, const __nv_bfloat16* __restrict__ wql,
                                                const __nv_bfloat16* __restrict__ wkh, const __nv_bfloat16* __restrict__ wkl,
                                                const __nv_bfloat16* __restrict__ wvh, const __nv_bfloat16* __restrict__ wvl,
                                                __nv_bfloat16* __restrict__ qh_o, __nv_bfloat16* __restrict__ ql_o,
                                                __nv_bfloat16* __restrict__ kh_o, __nv_bfloat16* __restrict__ kl_o,
                                                __nv_bfloat16* __restrict__ vh_o, __nv_bfloat16* __restrict__ vl_o,
                                                const float2* __restrict__ trig)
{
    extern __shared__ char sm[];
    const uint32_t smb = smem_u32(sm);
    const int tid  = threadIdx.x;
    const int wid  = tid >> 5;
    const int lane = tid & 31;
    const int brow = blockIdx.y;
    const int bcol = blockIdx.x;
    const int sel  = bcol >> 3;          // 0=q, 1=k, 2=v
    const int bc   = bcol & 7;
    const int wm = wid >> 2;
    const int wn = wid & 3;

    const __nv_bfloat16* Bh = (sel == 0) ? wqh : (sel == 1) ? wkh : wvh;
    const __nv_bfloat16* Bl = (sel == 0) ? wql : (sel == 1) ? wkl : wvl;
    __nv_bfloat16* Oh = (sel == 0) ? qh_o : (sel == 1) ? kh_o : vh_o;
    __nv_bfloat16* Ol = (sel == 0) ? ql_o : (sel == 1) ? kl_o : vl_o;

    const int lrow  = tid >> 1;
    const int lhalf = tid & 1;
    const size_t aoff = (size_t)(brow*128 + lrow)*GK;
    const size_t boff = (size_t)(bc*128 + lrow)*GK;
    uint32_t soff[2];
    soff[0] = sw_off(lrow, lhalf*2);
    soff[1] = sw_off(lrow, lhalf*2+1);

    const int l15 = lane & 15;
    const int l16 = lane >> 4;

    float acc[4][4][4];
    #pragma unroll
    for (int i = 0; i < 4; i++)
        #pragma unroll
        for (int j = 0; j < 4; j++)
            #pragma unroll
            for (int e = 0; e < 4; e++) acc[i][j][e] = 0.0f;

    gemm_mainloop(smb, xh, xl, Bh, Bl, aoff, boff, soff, lhalf, wm, wn, l15, l16, acc);

    // epilogue: RoPE (sel<2) + split + bf16 store
    const int rbase = brow*128 + wm*64 + (lane >> 2);
    const int cb    = bc*128 + wn*32 + (lane & 3)*2;   // col in [0,1024), even
    #pragma unroll
    for (int mt = 0; mt < 4; mt++) {
        #pragma unroll
        for (int nt = 0; nt < 4; nt++) {
            const int col = cb + nt*8;
            const int t   = (col & 63) >> 1;
            #pragma unroll
            for (int half = 0; half < 2; half++) {
                const int row = rbase + mt*16 + half*8;
                float e = acc[mt][nt][2*half];
                float o = acc[mt][nt][2*half+1];
                if (sel < 2) {
                    const float2 cs = trig[(row & (SEQ-1))*32 + t];
                    float re = e*cs.x - o*cs.y;
                    float ro = e*cs.y + o*cs.x;
                    if (sel == 0) { re *= QSCL; ro *= QSCL; }
                    e = re; o = ro;
                }
                uint32_t hw, lw;
                pack2(e, o, hw, lw);
                const size_t idx = ((size_t)row*D_MODEL + col) >> 1;
                ((uint32_t*)Oh)[idx] = hw;
                ((uint32_t*)Ol)[idx] = lw;
            }
        }
    }
}

// ===========================================================================
// Output-projection GEMM (fp32 C), identical mainloop.
// ===========================================================================
__global__ void __launch_bounds__(256, 2) gemm_pre(const __nv_bfloat16* __restrict__ Ah,
                                                const __nv_bfloat16* __restrict__ Al,
                                                const __nv_bfloat16* __restrict__ Bh,
                                                const __nv_bfloat16* __restrict__ Bl,
                                                float* __restrict__ C)
{
    extern __shared__ char sm[];
    const uint32_t smb = smem_u32(sm);
    const int tid  = threadIdx.x;
    const int wid  = tid >> 5;
    const int lane = tid & 31;
    const int brow = blockIdx.y;
    const int bcol = blockIdx.x;
    const int wm = wid >> 2;
    const int wn = wid & 3;

    const int lrow  = tid >> 1;
    const int lhalf = tid & 1;
    const size_t aoff = (size_t)(brow*128 + lrow)*GK;
    const size_t boff = (size_t)(bcol*128 + lrow)*GK;
    uint32_t soff[2];
    soff[0] = sw_off(lrow, lhalf*2);
    soff[1] = sw_off(lrow, lhalf*2+1);

    const int l15 = lane & 15;
    const int l16 = lane >> 4;

    float acc[4][4][4];
    #pragma unroll
    for (int i = 0; i < 4; i++)
        #pragma unroll
        for (int j = 0; j < 4; j++)
            #pragma unroll
            for (int e = 0; e < 4; e++) acc[i][j][e] = 0.0f;

    gemm_mainloop(smb, Ah, Al, Bh, Bl, aoff, boff, soff, lhalf, wm, wn, l15, l16, acc);

    const int rbase = brow*128 + wm*64 + (lane >> 2);
    const int cbase = bcol*128 + wn*32 + (lane & 3)*2;
    #pragma unroll
    for (int mt = 0; mt < 4; mt++) {
        #pragma unroll
        for (int nt = 0; nt < 4; nt++) {
            float* p = C + (size_t)(rbase + mt*16)*D_MODEL + cbase + nt*8;
            *(float2*)p = make_float2(acc[mt][nt][0], acc[mt][nt][1]);
            *(float2*)(p + 8*D_MODEL) = make_float2(acc[mt][nt][2], acc[mt][nt][3]);
        }
    }
}

// ===========================================================================
// Flash attention (causal), bf16x3 mma, pre-split inputs, cp.async pipelined.
// qtile REVERSED vs blockIdx.x so the largest causal CTAs launch first.
// ===========================================================================
#define FKVSTG 32768
#define FQH2   65536
#define FQL2   81920
#define FSMEM2 98304

__global__ void __launch_bounds__(256, 2) flash_mma(const __nv_bfloat16* __restrict__ qh_g,
                                                 const __nv_bfloat16* __restrict__ ql_g,
                                                 const __nv_bfloat16* __restrict__ kh_g,
                                                 const __nv_bfloat16* __restrict__ kl_g,
                                                 const __nv_bfloat16* __restrict__ vh_g,
                                                 const __nv_bfloat16* __restrict__ vl_g,
                                                 __nv_bfloat16* __restrict__ ath,
                                                 __nv_bfloat16* __restrict__ atl)
{
    extern __shared__ char smc[];
    const uint32_t smb = smem_u32(smc);
    const int tid  = threadIdx.x;
    const int wid  = tid >> 5;
    const int lane = tid & 31;
    const int qtile = (int)gridDim.x - 1 - (int)blockIdx.x;   // big CTAs first
    const int qt0  = qtile * 128;
    const int h    = blockIdx.y;
    const int b    = blockIdx.z;
    const size_t hoff = (size_t)h*HDIM;
    const size_t srow = (size_t)b*SEQ;

    // ---- prologue: Q tile + KV tile 0 ----
    {
        const int r = tid >> 1;
        const int half = tid & 1;
        const size_t ge = (srow + qt0 + r)*D_MODEL + hoff;
        #pragma unroll
        for (int u = 0; u < 4; u++) {
            const int chunk = half*4 + u;
            const uint32_t off = fsw(r, chunk);
            CP16(smb + FQH2 + off, qh_g + ge + chunk*8);
            CP16(smb + FQL2 + off, ql_g + ge + chunk*8);
        }
        CPCOMMIT();
    }
    {
        const int r = tid >> 2;
        const int qd = tid & 3;
        const size_t ge = (srow + r)*D_MODEL + hoff;
        #pragma unroll
        for (int u = 0; u < 2; u++) {
            const int chunk = qd*2 + u;
            const uint32_t off = fsw(r, chunk);
            CP16(smb + 0     + off, kh_g + ge + chunk*8);
            CP16(smb + 8192  + off, kl_g + ge + chunk*8);
            CP16(smb + 16384 + off, vh_g + ge + chunk*8);
            CP16(smb + 24576 + off, vl_g + ge + chunk*8);
        }
        CPCOMMIT();
    }
    CPWAIT0();
    __syncthreads();

    // ---- Q fragments (registers, whole kernel) ----
    uint32_t qh[4][4], ql[4][4];
    {
        const int r = wid*16 + (lane & 15);
        #pragma unroll
        for (int i = 0; i < 4; i++) {
            const uint32_t off = fsw(r, 2*i + (lane >> 4));
            ldsm_x4(qh[i], smb + FQH2 + off);
            ldsm_x4(ql[i], smb + FQL2 + off);
        }
    }

    float o[8][4];
    #pragma unroll
    for (int j = 0; j < 8; j++)
        #pragma unroll
        for (int e = 0; e < 4; e++) o[j][e] = 0.0f;
    float mrow[2] = {-INFINITY, -INFINITY};
    float lrow[2] = {0.0f, 0.0f};

    const int nkt = qtile*2 + 2;
    for (int kt = 0; kt < nkt; kt++) {
        if (kt + 1 < nkt) {
            const uint32_t s0 = smb + ((kt+1)&1)*FKVSTG;
            const int r = tid >> 2;
            const int qd = tid & 3;
            const size_t ge = (srow + (kt+1)*64 + r)*D_MODEL + hoff;
            #pragma unroll
            for (int u = 0; u < 2; u++) {
                const int chunk = qd*2 + u;
                const uint32_t off = fsw(r, chunk);
                CP16(s0 + 0     + off, kh_g + ge + chunk*8);
                CP16(s0 + 8192  + off, kl_g + ge + chunk*8);
                CP16(s0 + 16384 + off, vh_g + ge + chunk*8);
                CP16(s0 + 24576 + off, vl_g + ge + chunk*8);
            }
            CPCOMMIT();
        }

        if (kt*64 <= qt0 + wid*16 + 15) {
            const uint32_t st  = smb + (kt&1)*FKVSTG;
            const uint32_t uKh = st, uKl = st + 8192, uVh = st + 16384, uVl = st + 24576;

            float s[8][4];
            #pragma unroll
            for (int j = 0; j < 8; j++)
                #pragma unroll
                for (int e = 0; e < 4; e++) s[j][e] = 0.0f;

            #pragma unroll
            for (int i = 0; i < 4; i++) {
                uint32_t bh[4][4], bl[4][4];
                #pragma unroll
                for (int ng = 0; ng < 4; ng++) {
                    const int r = ng*16 + (lane & 15);
                    const uint32_t off = fsw(r, 2*i + (lane >> 4));
                    ldsm_x4(bh[ng], uKh + off);
                    ldsm_x4(bl[ng], uKl + off);
                }
                #pragma unroll
                for (int j = 0; j < 8; j++) {
                    const int ng = j >> 1, ix = j & 1;
                    const uint32_t b0h = bh[ng][ix], b1h = bh[ng][2+ix];
                    const uint32_t b0l = bl[ng][ix], b1l = bl[ng][2+ix];
                    mma_bf16(s[j], qh[i], b0h, b1h);
                    mma_bf16(s[j], ql[i], b0h, b1h);
                    mma_bf16(s[j], qh[i], b0l, b1l);
                }
            }

            if (kt*64 + 63 > qt0 + wid*16) {
                const int qr = qt0 + wid*16 + (lane >> 2);
                const int kc = kt*64 + (lane & 3)*2;
                #pragma unroll
                for (int j = 0; j < 8; j++) {
                    #pragma unroll
                    for (int e = 0; e < 4; e++) {
                        const int col = kc + j*8 + (e & 1);
                        const int row = qr + (e >> 1)*8;
                        if (col > row) s[j][e] = -INFINITY;
                    }
                }
            }

            #pragma unroll
            for (int hf = 0; hf < 2; hf++) {
                float mx = -INFINITY;
                #pragma unroll
                for (int j = 0; j < 8; j++)
                    mx = fmaxf(mx, fmaxf(s[j][2*hf], s[j][2*hf+1]));
                mx = fmaxf(mx, __shfl_xor_sync(0xffffffffu, mx, 1));
                mx = fmaxf(mx, __shfl_xor_sync(0xffffffffu, mx, 2));
                const float mn    = fmaxf(mrow[hf], mx);
                const float alpha = ex2f(mrow[hf] - mn);
                mrow[hf] = mn;
                float sum = 0.0f;
                #pragma unroll
                for (int j = 0; j < 8; j++) {
                    const float p0 = ex2f(s[j][2*hf]   - mn);
                    const float p1 = ex2f(s[j][2*hf+1] - mn);
                    s[j][2*hf] = p0; s[j][2*hf+1] = p1;
                    sum += p0 + p1;
                }
                sum += __shfl_xor_sync(0xffffffffu, sum, 1);
                sum += __shfl_xor_sync(0xffffffffu, sum, 2);
                lrow[hf] = lrow[hf]*alpha + sum;
                #pragma unroll
                for (int j = 0; j < 8; j++) {
                    o[j][2*hf]   *= alpha;
                    o[j][2*hf+1] *= alpha;
                }
            }

            uint32_t ph[4][4], pl[4][4];
            #pragma unroll
            for (int g = 0; g < 4; g++) {
                pack2(s[2*g][0],   s[2*g][1],   ph[g][0], pl[g][0]);
                pack2(s[2*g][2],   s[2*g][3],   ph[g][1], pl[g][1]);
                pack2(s[2*g+1][0], s[2*g+1][1], ph[g][2], pl[g][2]);
                pack2(s[2*g+1][2], s[2*g+1][3], ph[g][3], pl[g][3]);
            }

            #pragma unroll
            for (int g = 0; g < 4; g++) {
                uint32_t vh[4][4], vl[4][4];
                #pragma unroll
                for (int ng = 0; ng < 4; ng++) {
                    const int r = g*16 + (lane & 15);
                    const uint32_t off = fsw(r, 2*ng + (lane >> 4));
                    ldsm_x4_t(vh[ng], uVh + off);
                    ldsm_x4_t(vl[ng], uVl + off);
                }
                #pragma unroll
                for (int j = 0; j < 8; j++) {
                    const int ng = j >> 1, ix = j & 1;
                    const uint32_t b0h = vh[ng][2*ix], b1h = vh[ng][2*ix+1];
                    const uint32_t b0l = vl[ng][2*ix], b1l = vl[ng][2*ix+1];
                    mma_bf16(o[j], ph[g], b0h, b1h);
                    mma_bf16(o[j], pl[g], b0h, b1h);
                    mma_bf16(o[j], ph[g], b0l, b1l);
                }
            }
        }

        CPWAIT0();
        __syncthreads();
    }

    // ---- epilogue: normalize, split, write bf16 hi/lo att ----
    #pragma unroll
    for (int hf = 0; hf < 2; hf++) {
        const float inv = 1.0f / lrow[hf];
        const int row = qt0 + wid*16 + (lane >> 2) + hf*8;
        const size_t ebase = (srow + row)*D_MODEL + hoff + (lane & 3)*2;
        #pragma unroll
        for (int j = 0; j < 8; j++) {
            uint32_t hw, lw;
            pack2(o[j][2*hf]*inv, o[j][2*hf+1]*inv, hw, lw);
            ((uint32_t*)ath)[(ebase + j*8) >> 1] = hw;
            ((uint32_t*)atl)[(ebase + j*8) >> 1] = lw;
        }
    }
}

// ---------------------------------------------------------------------------
extern "C" void kernel_launch(void* const* d_in, const int* in_sizes, int n_in,
                              void* d_out, int out_size)
{
    (void)in_sizes; (void)n_in; (void)out_size;
    const float* x  = (const float*)d_in[0];
    const float* Wq = (const float*)d_in[1];
    const float* Wk = (const float*)d_in[2];
    const float* Wv = (const float*)d_in[3];
    const float* Wo = (const float*)d_in[4];
    float* out = (float*)d_out;

    __nv_bfloat16 *xh, *xl, *wqh, *wql, *wkh, *wkl, *wvh, *wvl, *woh, *wol;
    __nv_bfloat16 *qh, *ql, *kh, *kl, *vh, *vl, *ath, *atl;
    float2* trig;
    cudaGetSymbolAddress((void**)&xh,  g_xh);  cudaGetSymbolAddress((void**)&xl,  g_xl);
    cudaGetSymbolAddress((void**)&wqh, g_wqh); cudaGetSymbolAddress((void**)&wql, g_wql);
    cudaGetSymbolAddress((void**)&wkh, g_wkh); cudaGetSymbolAddress((void**)&wkl, g_wkl);
    cudaGetSymbolAddress((void**)&wvh, g_wvh); cudaGetSymbolAddress((void**)&wvl, g_wvl);
    cudaGetSymbolAddress((void**)&woh, g_woh); cudaGetSymbolAddress((void**)&wol, g_wol);
    cudaGetSymbolAddress((void**)&qh,  g_qh);  cudaGetSymbolAddress((void**)&ql,  g_ql);
    cudaGetSymbolAddress((void**)&kh,  g_kh);  cudaGetSymbolAddress((void**)&kl,  g_kl);
    cudaGetSymbolAddress((void**)&vh,  g_vh);  cudaGetSymbolAddress((void**)&vl,  g_vl);
    cudaGetSymbolAddress((void**)&ath, g_ath); cudaGetSymbolAddress((void**)&atl, g_atl);
    cudaGetSymbolAddress((void**)&trig, g_trig);

    cudaFuncSetAttribute(gemm_qkv,  cudaFuncAttributeMaxDynamicSharedMemorySize, GSMEM2);
    cudaFuncSetAttribute(gemm_pre,  cudaFuncAttributeMaxDynamicSharedMemorySize, GSMEM2);
    cudaFuncSetAttribute(flash_mma, cudaFuncAttributeMaxDynamicSharedMemorySize, FSMEM2);

    // 1) trig table + split inputs/weights to bf16 hi/lo
    trig_kernel<<<(SEQ*(HDIM/2) + 255)/256, 256>>>(trig);
    const int tot_pairs = XPAIRS + 4*WPAIRS;
    split_all<<<(tot_pairs + 255)/256, 256>>>(x, Wq, Wk, Wv, Wo,
                                              xh, xl, wqh, wql, wkh, wkl,
                                              wvh, wvl, woh, wol);

    // 2) Fused QKV projections + RoPE + split -> bf16 hi/lo q/k/v
    gemm_qkv<<<dim3(24, MTOT/128), 256, GSMEM2>>>(xh, xl, wqh, wql, wkh, wkl, wvh, wvl,
                                                  qh, ql, kh, kl, vh, vl, trig);

    // 3) Causal flash attention -> att bf16 hi/lo
    flash_mma<<<dim3(SEQ/128, NHEADS, BATCH), 256, FSMEM2>>>(qh, ql, kh, kl, vh, vl, ath, atl);

    // 4) Output projection -> fp32 out
    gemm_pre<<<dim3(D_MODEL/128, MTOT/128), 256, GSMEM2>>>(ath, atl, woh, wol, out);
}

// round 13
// speedup vs baseline: 1.0062x; 1.0062x over previous
#include <cuda_runtime.h>
#include <cuda_bf16.h>
#include <math.h>
#include <stdint.h>

#define D_MODEL 1024
#define NHEADS  16
#define HDIM    64
#define BATCH   2
#define SEQ     2048
#define MTOT    (BATCH*SEQ)          // 4096
#define GK      1024
#define NELEM   (MTOT*D_MODEL)       // 4M
#define WELEM   (D_MODEL*D_MODEL)    // 1M

// Scratch (allocation-free rule: static __device__ globals)
__device__ __nv_bfloat16 g_xh[NELEM],  g_xl[NELEM];
__device__ __nv_bfloat16 g_wqh[WELEM], g_wql[WELEM];
__device__ __nv_bfloat16 g_wkh[WELEM], g_wkl[WELEM];
__device__ __nv_bfloat16 g_wvh[WELEM], g_wvl[WELEM];
__device__ __nv_bfloat16 g_woh[WELEM], g_wol[WELEM];
__device__ __nv_bfloat16 g_qh[NELEM],  g_ql[NELEM];
__device__ __nv_bfloat16 g_kh[NELEM],  g_kl[NELEM];
__device__ __nv_bfloat16 g_vh[NELEM],  g_vl[NELEM];
__device__ __nv_bfloat16 g_ath[NELEM], g_atl[NELEM];
__device__ float2 g_trig[SEQ*(HDIM/2)];   // [s][t] -> (cos, sin)

// ===========================================================================
// helpers
// ===========================================================================
__device__ __forceinline__ uint32_t smem_u32(const void* p) {
    uint32_t a;
    asm("{ .reg .u64 t; cvta.to.shared.u64 t, %1; cvt.u32.u64 %0, t; }" : "=r"(a) : "l"(p));
    return a;
}
__device__ __forceinline__ void ldsm_x4(uint32_t* r, uint32_t addr) {
    asm volatile("ldmatrix.sync.aligned.m8n8.x4.shared.b16 {%0,%1,%2,%3}, [%4];"
        : "=r"(r[0]), "=r"(r[1]), "=r"(r[2]), "=r"(r[3]) : "r"(addr));
}
__device__ __forceinline__ void ldsm_x4_t(uint32_t* r, uint32_t addr) {
    asm volatile("ldmatrix.sync.aligned.m8n8.x4.trans.shared.b16 {%0,%1,%2,%3}, [%4];"
        : "=r"(r[0]), "=r"(r[1]), "=r"(r[2]), "=r"(r[3]) : "r"(addr));
}
__device__ __forceinline__ void mma_bf16(float* c, const uint32_t* a, uint32_t b0, uint32_t b1) {
    asm volatile("mma.sync.aligned.m16n8k16.row.col.f32.bf16.bf16.f32 "
        "{%0,%1,%2,%3}, {%4,%5,%6,%7}, {%8,%9}, {%0,%1,%2,%3};"
        : "+f"(c[0]), "+f"(c[1]), "+f"(c[2]), "+f"(c[3])
        : "r"(a[0]), "r"(a[1]), "r"(a[2]), "r"(a[3]), "r"(b0), "r"(b1));
}
__device__ __forceinline__ float ex2f(float x) {
    float y; asm("ex2.approx.f32 %0, %1;" : "=f"(y) : "f"(x)); return y;
}
__device__ __forceinline__ void pack2(float x, float y, uint32_t& h, uint32_t& l) {
    __nv_bfloat162 hh = __floats2bfloat162_rn(x, y);
    float hx = __bfloat162float(hh.x), hy = __bfloat162float(hh.y);
    __nv_bfloat162 ll = __floats2bfloat162_rn(x - hx, y - hy);
    h = *(uint32_t*)&hh; l = *(uint32_t*)&ll;
}

#define CP16(dst, src) \
    asm volatile("cp.async.cg.shared.global [%0], [%1], 16;" :: "r"(dst), "l"(src) : "memory")
#define CPCOMMIT() asm volatile("cp.async.commit_group;" ::: "memory")
#define CPWAIT0()  asm volatile("cp.async.wait_group 0;" ::: "memory")

#define QSCL 0.18033688011112042f   // 0.125 * log2(e)

// ===========================================================================
// split_all: fp32 -> bf16 hi/lo for x + 4 weights, PLUS trig table, one launch.
// index space: [0,2M) x pairs; [2M,4M) weight pairs; [4M,4M+65536) trig.
// ===========================================================================
#define XPAIRS (NELEM/2)
#define WPAIRS (WELEM/2)
#define TRIGN  (SEQ*(HDIM/2))

__global__ void split_all(const float* __restrict__ x,
                          const float* __restrict__ Wq, const float* __restrict__ Wk,
                          const float* __restrict__ Wv, const float* __restrict__ Wo,
                          __nv_bfloat16* xh, __nv_bfloat16* xl,
                          __nv_bfloat16* wqh, __nv_bfloat16* wql,
                          __nv_bfloat16* wkh, __nv_bfloat16* wkl,
                          __nv_bfloat16* wvh, __nv_bfloat16* wvl,
                          __nv_bfloat16* woh, __nv_bfloat16* wol,
                          float2* __restrict__ trig)
{
    int i = blockIdx.x*blockDim.x + threadIdx.x;
    const int total = XPAIRS + 4*WPAIRS;
    if (i >= total) {
        const int j = i - total;
        if (j < TRIGN) {
            const int t = j & 31;
            const int s = j >> 5;
            const float ang = (float)s * exp2f((float)t * (-2.0f/(float)HDIM) * 13.28771237954945f);
            float sn, cs;
            sincosf(ang, &sn, &cs);
            trig[j] = make_float2(cs, sn);
        }
        return;
    }

    const float* src; __nv_bfloat16 *hi, *lo; int j;
    if (i < XPAIRS)                { src = x;  hi = xh;  lo = xl;  j = i; }
    else if (i < XPAIRS+WPAIRS)    { src = Wq; hi = wqh; lo = wql; j = i - XPAIRS; }
    else if (i < XPAIRS+2*WPAIRS)  { src = Wk; hi = wkh; lo = wkl; j = i - XPAIRS - WPAIRS; }
    else if (i < XPAIRS+3*WPAIRS)  { src = Wv; hi = wvh; lo = wvl; j = i - XPAIRS - 2*WPAIRS; }
    else                           { src = Wo; hi = woh; lo = wol; j = i - XPAIRS - 3*WPAIRS; }

    float2 v = *(const float2*)(src + 2*(size_t)j);
    uint32_t h, l;
    pack2(v.x, v.y, h, l);
    ((uint32_t*)hi)[j] = h;
    ((uint32_t*)lo)[j] = l;
}

// ===========================================================================
// swizzles
// ===========================================================================
__device__ __forceinline__ uint32_t sw_off(int row, int chunk) {
    return (uint32_t)(row*64 + ((chunk ^ ((row>>1)&3))<<4));
}
__device__ __forceinline__ uint32_t fsw(int row, int chunk) {
    return (uint32_t)(row*128 + ((chunk ^ (row & 7)) << 4));
}

#define STAGE2 32768
#define GSMEM2 65536

// ===========================================================================
// GEMM mainloop shared by both GEMM kernels (acc += (Ah+Al)(Bh+Bl), 3 passes)
// ===========================================================================
__device__ __forceinline__ void gemm_mainloop(
    uint32_t smb, const __nv_bfloat16* Ah, const __nv_bfloat16* Al,
    const __nv_bfloat16* Bh, const __nv_bfloat16* Bl,
    size_t aoff, size_t boff, const uint32_t* soff,
    int lhalf, int wm, int wn, int l15, int l16, float acc[4][4][4])
{
    // prologue: chunk 0 -> stage 0
    {
        const uint32_t s0 = smb;
        #pragma unroll
        for (int u = 0; u < 2; u++) {
            const int chunk = lhalf*2 + u;
            const size_t ke = (size_t)chunk*8;
            CP16(s0 + 0     + soff[u], Ah + aoff + ke);
            CP16(s0 + 8192  + soff[u], Al + aoff + ke);
            CP16(s0 + 16384 + soff[u], Bh + boff + ke);
            CP16(s0 + 24576 + soff[u], Bl + boff + ke);
        }
        CPCOMMIT();
    }

    for (int ch = 0; ch < 32; ch++) {
        CPWAIT0();
        __syncthreads();

        if (ch < 31) {
            const uint32_t s0 = smb + ((ch+1)&1)*STAGE2;
            #pragma unroll
            for (int u = 0; u < 2; u++) {
                const int chunk = lhalf*2 + u;
                const size_t ke = (size_t)(ch+1)*32 + chunk*8;
                CP16(s0 + 0     + soff[u], Ah + aoff + ke);
                CP16(s0 + 8192  + soff[u], Al + aoff + ke);
                CP16(s0 + 16384 + soff[u], Bh + boff + ke);
                CP16(s0 + 24576 + soff[u], Bl + boff + ke);
            }
            CPCOMMIT();
        }

        const uint32_t st  = smb + (ch&1)*STAGE2;
        const uint32_t uAh = st, uAl = st + 8192, uBh = st + 16384, uBl = st + 24576;

        #pragma unroll
        for (int s = 0; s < 2; s++) {
            const int chunk = s*2 + l16;

            uint32_t bh[2][4], bl[2][4];
            #pragma unroll
            for (int ng = 0; ng < 2; ng++) {
                const int br = wn*32 + ng*16 + l15;
                const uint32_t off = sw_off(br, chunk);
                ldsm_x4(bh[ng], uBh + off);
                ldsm_x4(bl[ng], uBl + off);
            }

            #pragma unroll
            for (int mt = 0; mt < 4; mt++) {
                const int ar = wm*64 + mt*16 + l15;
                const uint32_t off = sw_off(ar, chunk);
                uint32_t ah[4], al[4];
                ldsm_x4(ah, uAh + off);
                ldsm_x4(al, uAl + off);

                #pragma unroll
                for (int nt = 0; nt < 4; nt++) {
                    const int ng = nt >> 1, ix = nt & 1;
                    const uint32_t b0h = bh[ng][ix], b1h = bh[ng][2+ix];
                    const uint32_t b0l = bl[ng][ix], b1l = bl[ng][2+ix];
                    mma_bf16(acc[mt][nt], ah, b0h, b1h);
                    mma_bf16(acc[mt][nt], al, b0h, b1h);
                    mma_bf16(acc[mt][nt], ah, b0l, b1l);
                }
            }
        }
    }
}

// ===========================================================================
// Fused QKV GEMM: grid (24, 32). bcol>>3 selects Wq/Wk/Wv; epilogue applies
// RoPE (q,k; q also scaled) via trig table and writes bf16 hi/lo directly.
// ===========================================================================
__global__ void __launch_bounds__(256) gemm_qkv(const __nv_bfloat16* __restrict__ xh,
                                                const __nv_bfloat16* __restrict__ xl,
                                                const __nv_bfloat16* __restrict__ wqh, const __nv_bfloat16* __restrict__ wql,
                                                const __nv_bfloat16* __restrict__ wkh, const __nv_bfloat16* __restrict__ wkl,
                                                const __nv_bfloat16* __restrict__ wvh, const __nv_bfloat16* __restrict__ wvl,
                                                __nv_bfloat16* __restrict__ qh_o, __nv_bfloat16* __restrict__ ql_o,
                                                __nv_bfloat16* __restrict__ kh_o, __nv_bfloat16* __restrict__ kl_o,
                                                __nv_bfloat16* __restrict__ vh_o, __nv_bfloat16* __restrict__ vl_o,
                                                const float2* __restrict__ trig)
{
    extern __shared__ char sm[];
    const uint32_t smb = smem_u32(sm);
    const int tid  = threadIdx.x;
    const int wid  = tid >> 5;
    const int lane = tid & 31;
    const int brow = blockIdx.y;
    const int bcol = blockIdx.x;
    const int sel  = bcol >> 3;          // 0=q, 1=k, 2=v
    const int bc   = bcol & 7;
    const int wm = wid >> 2;
    const int wn = wid & 3;

    const __nv_bfloat16* Bh = (sel == 0) ? wqh : (sel == 1) ? wkh : wvh;
    const __nv_bfloat16* Bl = (sel == 0) ? wql : (sel == 1) ? wkl : wvl;
    __nv_bfloat16* Oh = (sel == 0) ? qh_o : (sel == 1) ? kh_o : vh_o;
    __nv_bfloat16* Ol = (sel == 0) ? ql_o : (sel == 1) ? kl_o : vl_o;

    const int lrow  = tid >> 1;
    const int lhalf = tid & 1;
    const size_t aoff = (size_t)(brow*128 + lrow)*GK;
    const size_t boff = (size_t)(bc*128 + lrow)*GK;
    uint32_t soff[2];
    soff[0] = sw_off(lrow, lhalf*2);
    soff[1] = sw_off(lrow, lhalf*2+1);

    const int l15 = lane & 15;
    const int l16 = lane >> 4;

    float acc[4][4][4];
    #pragma unroll
    for (int i = 0; i < 4; i++)
        #pragma unroll
        for (int j = 0; j < 4; j++)
            #pragma unroll
            for (int e = 0; e < 4; e++) acc[i][j][e] = 0.0f;

    gemm_mainloop(smb, xh, xl, Bh, Bl, aoff, boff, soff, lhalf, wm, wn, l15, l16, acc);

    // epilogue: RoPE (sel<2) + split + bf16 store
    const int rbase = brow*128 + wm*64 + (lane >> 2);
    const int cb    = bc*128 + wn*32 + (lane & 3)*2;   // col in [0,1024), even
    #pragma unroll
    for (int mt = 0; mt < 4; mt++) {
        #pragma unroll
        for (int nt = 0; nt < 4; nt++) {
            const int col = cb + nt*8;
            const int t   = (col & 63) >> 1;
            #pragma unroll
            for (int half = 0; half < 2; half++) {
                const int row = rbase + mt*16 + half*8;
                float e = acc[mt][nt][2*half];
                float o = acc[mt][nt][2*half+1];
                if (sel < 2) {
                    const float2 cs = trig[(row & (SEQ-1))*32 + t];
                    float re = e*cs.x - o*cs.y;
                    float ro = e*cs.y + o*cs.x;
                    if (sel == 0) { re *= QSCL; ro *= QSCL; }
                    e = re; o = ro;
                }
                uint32_t hw, lw;
                pack2(e, o, hw, lw);
                const size_t idx = ((size_t)row*D_MODEL + col) >> 1;
                ((uint32_t*)Oh)[idx] = hw;
                ((uint32_t*)Ol)[idx] = lw;
            }
        }
    }
}

// ===========================================================================
// Output-projection GEMM (fp32 C), identical mainloop.
// ===========================================================================
__global__ void __launch_bounds__(256) gemm_pre(const __nv_bfloat16* __restrict__ Ah,
                                                const __nv_bfloat16* __restrict__ Al,
                                                const __nv_bfloat16* __restrict__ Bh,
                                                const __nv_bfloat16* __restrict__ Bl,
                                                float* __restrict__ C)
{
    extern __shared__ char sm[];
    const uint32_t smb = smem_u32(sm);
    const int tid  = threadIdx.x;
    const int wid  = tid >> 5;
    const int lane = tid & 31;
    const int brow = blockIdx.y;
    const int bcol = blockIdx.x;
    const int wm = wid >> 2;
    const int wn = wid & 3;

    const int lrow  = tid >> 1;
    const int lhalf = tid & 1;
    const size_t aoff = (size_t)(brow*128 + lrow)*GK;
    const size_t boff = (size_t)(bcol*128 + lrow)*GK;
    uint32_t soff[2];
    soff[0] = sw_off(lrow, lhalf*2);
    soff[1] = sw_off(lrow, lhalf*2+1);

    const int l15 = lane & 15;
    const int l16 = lane >> 4;

    float acc[4][4][4];
    #pragma unroll
    for (int i = 0; i < 4; i++)
        #pragma unroll
        for (int j = 0; j < 4; j++)
            #pragma unroll
            for (int e = 0; e < 4; e++) acc[i][j][e] = 0.0f;

    gemm_mainloop(smb, Ah, Al, Bh, Bl, aoff, boff, soff, lhalf, wm, wn, l15, l16, acc);

    const int rbase = brow*128 + wm*64 + (lane >> 2);
    const int cbase = bcol*128 + wn*32 + (lane & 3)*2;
    #pragma unroll
    for (int mt = 0; mt < 4; mt++) {
        #pragma unroll
        for (int nt = 0; nt < 4; nt++) {
            float* p = C + (size_t)(rbase + mt*16)*D_MODEL + cbase + nt*8;
            *(float2*)p = make_float2(acc[mt][nt][0], acc[mt][nt][1]);
            *(float2*)(p + 8*D_MODEL) = make_float2(acc[mt][nt][2], acc[mt][nt][3]);
        }
    }
}

// ===========================================================================
// Flash attention (causal), bf16x3 mma, pre-split inputs, cp.async pipelined.
// qtile REVERSED vs blockIdx.x so the largest causal CTAs launch first.
// ===========================================================================
#define FKVSTG 32768
#define FQH2   65536
#define FQL2   81920
#define FSMEM2 98304

__global__ void __launch_bounds__(256, 2) flash_mma(const __nv_bfloat16* __restrict__ qh_g,
                                                 const __nv_bfloat16* __restrict__ ql_g,
                                                 const __nv_bfloat16* __restrict__ kh_g,
                                                 const __nv_bfloat16* __restrict__ kl_g,
                                                 const __nv_bfloat16* __restrict__ vh_g,
                                                 const __nv_bfloat16* __restrict__ vl_g,
                                                 __nv_bfloat16* __restrict__ ath,
                                                 __nv_bfloat16* __restrict__ atl)
{
    extern __shared__ char smc[];
    const uint32_t smb = smem_u32(smc);
    const int tid  = threadIdx.x;
    const int wid  = tid >> 5;
    const int lane = tid & 31;
    const int qtile = (int)gridDim.x - 1 - (int)blockIdx.x;   // big CTAs first
    const int qt0  = qtile * 128;
    const int h    = blockIdx.y;
    const int b    = blockIdx.z;
    const size_t hoff = (size_t)h*HDIM;
    const size_t srow = (size_t)b*SEQ;

    // ---- prologue: Q tile + KV tile 0 ----
    {
        const int r = tid >> 1;
        const int half = tid & 1;
        const size_t ge = (srow + qt0 + r)*D_MODEL + hoff;
        #pragma unroll
        for (int u = 0; u < 4; u++) {
            const int chunk = half*4 + u;
            const uint32_t off = fsw(r, chunk);
            CP16(smb + FQH2 + off, qh_g + ge + chunk*8);
            CP16(smb + FQL2 + off, ql_g + ge + chunk*8);
        }
        CPCOMMIT();
    }
    {
        const int r = tid >> 2;
        const int qd = tid & 3;
        const size_t ge = (srow + r)*D_MODEL + hoff;
        #pragma unroll
        for (int u = 0; u < 2; u++) {
            const int chunk = qd*2 + u;
            const uint32_t off = fsw(r, chunk);
            CP16(smb + 0     + off, kh_g + ge + chunk*8);
            CP16(smb + 8192  + off, kl_g + ge + chunk*8);
            CP16(smb + 16384 + off, vh_g + ge + chunk*8);
            CP16(smb + 24576 + off, vl_g + ge + chunk*8);
        }
        CPCOMMIT();
    }
    CPWAIT0();
    __syncthreads();

    // ---- Q fragments (registers, whole kernel) ----
    uint32_t qh[4][4], ql[4][4];
    {
        const int r = wid*16 + (lane & 15);
        #pragma unroll
        for (int i = 0; i < 4; i++) {
            const uint32_t off = fsw(r, 2*i + (lane >> 4));
            ldsm_x4(qh[i], smb + FQH2 + off);
            ldsm_x4(ql[i], smb + FQL2 + off);
        }
    }

    float o[8][4];
    #pragma unroll
    for (int j = 0; j < 8; j++)
        #pragma unroll
        for (int e = 0; e < 4; e++) o[j][e] = 0.0f;
    float mrow[2] = {-INFINITY, -INFINITY};
    float lrow[2] = {0.0f, 0.0f};

    const int nkt = qtile*2 + 2;
    for (int kt = 0; kt < nkt; kt++) {
        if (kt + 1 < nkt) {
            const uint32_t s0 = smb + ((kt+1)&1)*FKVSTG;
            const int r = tid >> 2;
            const int qd = tid & 3;
            const size_t ge = (srow + (kt+1)*64 + r)*D_MODEL + hoff;
            #pragma unroll
            for (int u = 0; u < 2; u++) {
                const int chunk = qd*2 + u;
                const uint32_t off = fsw(r, chunk);
                CP16(s0 + 0     + off, kh_g + ge + chunk*8);
                CP16(s0 + 8192  + off, kl_g + ge + chunk*8);
                CP16(s0 + 16384 + off, vh_g + ge + chunk*8);
                CP16(s0 + 24576 + off, vl_g + ge + chunk*8);
            }
            CPCOMMIT();
        }

        if (kt*64 <= qt0 + wid*16 + 15) {
            const uint32_t st  = smb + (kt&1)*FKVSTG;
            const uint32_t uKh = st, uKl = st + 8192, uVh = st + 16384, uVl = st + 24576;

            float s[8][4];
            #pragma unroll
            for (int j = 0; j < 8; j++)
                #pragma unroll
                for (int e = 0; e < 4; e++) s[j][e] = 0.0f;

            #pragma unroll
            for (int i = 0; i < 4; i++) {
                uint32_t bh[4][4], bl[4][4];
                #pragma unroll
                for (int ng = 0; ng < 4; ng++) {
                    const int r = ng*16 + (lane & 15);
                    const uint32_t off = fsw(r, 2*i + (lane >> 4));
                    ldsm_x4(bh[ng], uKh + off);
                    ldsm_x4(bl[ng], uKl + off);
                }
                #pragma unroll
                for (int j = 0; j < 8; j++) {
                    const int ng = j >> 1, ix = j & 1;
                    const uint32_t b0h = bh[ng][ix], b1h = bh[ng][2+ix];
                    const uint32_t b0l = bl[ng][ix], b1l = bl[ng][2+ix];
                    mma_bf16(s[j], qh[i], b0h, b1h);
                    mma_bf16(s[j], ql[i], b0h, b1h);
                    mma_bf16(s[j], qh[i], b0l, b1l);
                }
            }

            if (kt*64 + 63 > qt0 + wid*16) {
                const int qr = qt0 + wid*16 + (lane >> 2);
                const int kc = kt*64 + (lane & 3)*2;
                #pragma unroll
                for (int j = 0; j < 8; j++) {
                    #pragma unroll
                    for (int e = 0; e < 4; e++) {
                        const int col = kc + j*8 + (e & 1);
                        const int row = qr + (e >> 1)*8;
                        if (col > row) s[j][e] = -INFINITY;
                    }
                }
            }

            #pragma unroll
            for (int hf = 0; hf < 2; hf++) {
                float mx = -INFINITY;
                #pragma unroll
                for (int j = 0; j < 8; j++)
                    mx = fmaxf(mx, fmaxf(s[j][2*hf], s[j][2*hf+1]));
                mx = fmaxf(mx, __shfl_xor_sync(0xffffffffu, mx, 1));
                mx = fmaxf(mx, __shfl_xor_sync(0xffffffffu, mx, 2));
                const float mn    = fmaxf(mrow[hf], mx);
                const float alpha = ex2f(mrow[hf] - mn);
                mrow[hf] = mn;
                float sum = 0.0f;
                #pragma unroll
                for (int j = 0; j < 8; j++) {
                    const float p0 = ex2f(s[j][2*hf]   - mn);
                    const float p1 = ex2f(s[j][2*hf+1] - mn);
                    s[j][2*hf] = p0; s[j][2*hf+1] = p1;
                    sum += p0 + p1;
                }
                sum += __shfl_xor_sync(0xffffffffu, sum, 1);
                sum += __shfl_xor_sync(0xffffffffu, sum, 2);
                lrow[hf] = lrow[hf]*alpha + sum;
                #pragma unroll
                for (int j = 0; j < 8; j++) {
                    o[j][2*hf]   *= alpha;
                    o[j][2*hf+1] *= alpha;
                }
            }

            uint32_t ph[4][4], pl[4][4];
            #pragma unroll
            for (int g = 0; g < 4; g++) {
                pack2(s[2*g][0],   s[2*g][1],   ph[g][0], pl[g][0]);
                pack2(s[2*g][2],   s[2*g][3],   ph[g][1], pl[g][1]);
                pack2(s[2*g+1][0], s[2*g+1][1], ph[g][2], pl[g][2]);
                pack2(s[2*g+1][2], s[2*g+1][3], ph[g][3], pl[g][3]);
            }

            #pragma unroll
            for (int g = 0; g < 4; g++) {
                uint32_t vh[4][4], vl[4][4];
                #pragma unroll
                for (int ng = 0; ng < 4; ng++) {
                    const int r = g*16 + (lane & 15);
                    const uint32_t off = fsw(r, 2*ng + (lane >> 4));
                    ldsm_x4_t(vh[ng], uVh + off);
                    ldsm_x4_t(vl[ng], uVl + off);
                }
                #pragma unroll
                for (int j = 0; j < 8; j++) {
                    const int ng = j >> 1, ix = j & 1;
                    const uint32_t b0h = vh[ng][2*ix], b1h = vh[ng][2*ix+1];
                    const uint32_t b0l = vl[ng][2*ix], b1l = vl[ng][2*ix+1];
                    mma_bf16(o[j], ph[g], b0h, b1h);
                    mma_bf16(o[j], pl[g], b0h, b1h);
                    mma_bf16(o[j], ph[g], b0l, b1l);
                }
            }
        }

        CPWAIT0();
        __syncthreads();
    }

    // ---- epilogue: normalize, split, write bf16 hi/lo att ----
    #pragma unroll
    for (int hf = 0; hf < 2; hf++) {
        const float inv = 1.0f / lrow[hf];
        const int row = qt0 + wid*16 + (lane >> 2) + hf*8;
        const size_t ebase = (srow + row)*D_MODEL + hoff + (lane & 3)*2;
        #pragma unroll
        for (int j = 0; j < 8; j++) {
            uint32_t hw, lw;
            pack2(o[j][2*hf]*inv, o[j][2*hf+1]*inv, hw, lw);
            ((uint32_t*)ath)[(ebase + j*8) >> 1] = hw;
            ((uint32_t*)atl)[(ebase + j*8) >> 1] = lw;
        }
    }
}

// ---------------------------------------------------------------------------
extern "C" void kernel_launch(void* const* d_in, const int* in_sizes, int n_in,
                              void* d_out, int out_size)
{
    (void)in_sizes; (void)n_in; (void)out_size;
    const float* x  = (const float*)d_in[0];
    const float* Wq = (const float*)d_in[1];
    const float* Wk = (const float*)d_in[2];
    const float* Wv = (const float*)d_in[3];
    const float* Wo = (const float*)d_in[4];
    float* out = (float*)d_out;

    __nv_bfloat16 *xh, *xl, *wqh, *wql, *wkh, *wkl, *wvh, *wvl, *woh, *wol;
    __nv_bfloat16 *qh, *ql, *kh, *kl, *vh, *vl, *ath, *atl;
    float2* trig;
    cudaGetSymbolAddress((void**)&xh,  g_xh);  cudaGetSymbolAddress((void**)&xl,  g_xl);
    cudaGetSymbolAddress((void**)&wqh, g_wqh); cudaGetSymbolAddress((void**)&wql, g_wql);
    cudaGetSymbolAddress((void**)&wkh, g_wkh); cudaGetSymbolAddress((void**)&wkl, g_wkl);
    cudaGetSymbolAddress((void**)&wvh, g_wvh); cudaGetSymbolAddress((void**)&wvl, g_wvl);
    cudaGetSymbolAddress((void**)&woh, g_woh); cudaGetSymbolAddress((void**)&wol, g_wol);
    cudaGetSymbolAddress((void**)&qh,  g_qh);  cudaGetSymbolAddress((void**)&ql,  g_ql);
    cudaGetSymbolAddress((void**)&kh,  g_kh);  cudaGetSymbolAddress((void**)&kl,  g_kl);
    cudaGetSymbolAddress((void**)&vh,  g_vh);  cudaGetSymbolAddress((void**)&vl,  g_vl);
    cudaGetSymbolAddress((void**)&ath, g_ath); cudaGetSymbolAddress((void**)&atl, g_atl);
    cudaGetSymbolAddress((void**)&trig, g_trig);

    cudaFuncSetAttribute(gemm_qkv,  cudaFuncAttributeMaxDynamicSharedMemorySize, GSMEM2);
    cudaFuncSetAttribute(gemm_pre,  cudaFuncAttributeMaxDynamicSharedMemorySize, GSMEM2);
    cudaFuncSetAttribute(flash_mma, cudaFuncAttributeMaxDynamicSharedMemorySize, FSMEM2);

    // 1) split inputs/weights to bf16 hi/lo + trig table (single launch)
    const int tot_threads = XPAIRS + 4*WPAIRS + TRIGN;
    split_all<<<(tot_threads + 255)/256, 256>>>(x, Wq, Wk, Wv, Wo,
                                                xh, xl, wqh, wql, wkh, wkl,
                                                wvh, wvl, woh, wol, trig);

    // 2) Fused QKV projections + RoPE + split -> bf16 hi/lo q/k/v
    gemm_qkv<<<dim3(24, MTOT/128), 256, GSMEM2>>>(xh, xl, wqh, wql, wkh, wkl, wvh, wvl,
                                                  qh, ql, kh, kl, vh, vl, trig);

    // 3) Causal flash attention -> att bf16 hi/lo
    flash_mma<<<dim3(SEQ/128, NHEADS, BATCH), 256, FSMEM2>>>(qh, ql, kh, kl, vh, vl, ath, atl);

    // 4) Output projection -> fp32 out
    gemm_pre<<<dim3(D_MODEL/128, MTOT/128), 256, GSMEM2>>>(ath, atl, woh, wol, out);
}